// round 12
// baseline (speedup 1.0000x reference)
#include <cuda_runtime.h>
#include <cuda_bf16.h>
#include <cstdint>
#include <cstddef>

#define B_    8192
#define NNEG  8192
#define D_    1024

#define BM 128
#define BN 128
#define BKB 128               // K-chunk in BYTES (= 128 s8 elems)
#define NIT    (D_ / BKB)     // 8
#define NTILES (NNEG / BN)    // 64

#define LDK 144               // smem row stride bytes (conflict-free ldmatrix)
#define STAGE_B (256 * LDK)   // A(128 rows)+B(128 rows) = 36864 B
#define NSTAGE 3
#define SMEM_BYTES (NSTAGE * STAGE_B)   // 110592
#define EPI_LD 132
#define CS_OFF (BM * EPI_LD * 4)        // col-scale array after C buffer (67584)

__device__ __align__(16) int8_t g_Qs8[(size_t)B_ * D_];
__device__ __align__(16) int8_t g_Ns8[(size_t)NNEG * D_];
__device__ float g_Qsc[B_];
__device__ float g_Nsc[NNEG];
__device__ float g_pos[B_];
__device__ float g_part[(size_t)B_ * NTILES];
__device__ float g_row[B_];

__constant__ float c_invT = 1.0f / 0.92f;

// ---------------------------------------------------------------------------
// Kernel 1: per-row ||q||,||p||,q.p -> pos_sim; quantize normalized Q to s8
// ---------------------------------------------------------------------------
__global__ void k_norm_qp(const float* __restrict__ q, const float* __restrict__ p) {
    int b = blockIdx.x, t = threadIdx.x;
    float4 a = reinterpret_cast<const float4*>(q + (size_t)b * D_)[t];
    float4 c = reinterpret_cast<const float4*>(p + (size_t)b * D_)[t];

    float qq = a.x*a.x + a.y*a.y + a.z*a.z + a.w*a.w;
    float pp = c.x*c.x + c.y*c.y + c.z*c.z + c.w*c.w;
    float qp = a.x*c.x + a.y*c.y + a.z*c.z + a.w*c.w;
    #pragma unroll
    for (int o = 16; o > 0; o >>= 1) {
        qq += __shfl_xor_sync(0xffffffffu, qq, o);
        pp += __shfl_xor_sync(0xffffffffu, pp, o);
        qp += __shfl_xor_sync(0xffffffffu, qp, o);
    }
    __shared__ float sq[8], sp[8], sc[8];
    __shared__ float s_inv, s_qs;
    int w = t >> 5, l = t & 31;
    if (l == 0) { sq[w] = qq; sp[w] = pp; sc[w] = qp; }
    __syncthreads();
    if (t == 0) {
        float QQ = 0.f, PP = 0.f, QP = 0.f;
        #pragma unroll
        for (int i = 0; i < 8; i++) { QQ += sq[i]; PP += sp[i]; QP += sc[i]; }
        float qn = sqrtf(QQ), pn = sqrtf(PP);
        g_pos[b] = QP / fmaxf(qn * pn, 1e-6f);
        s_inv = (qn > 0.f) ? (1.0f / qn) : 0.f;
    }
    __syncthreads();
    float inv = s_inv;
    float nx = a.x * inv, ny = a.y * inv, nz = a.z * inv, nw = a.w * inv;

    float m = fmaxf(fmaxf(fabsf(nx), fabsf(ny)), fmaxf(fabsf(nz), fabsf(nw)));
    #pragma unroll
    for (int o = 16; o > 0; o >>= 1) m = fmaxf(m, __shfl_xor_sync(0xffffffffu, m, o));
    if (l == 0) sq[w] = m;
    __syncthreads();
    if (t == 0) {
        float vmax = 0.f;
        #pragma unroll
        for (int i = 0; i < 8; i++) vmax = fmaxf(vmax, sq[i]);
        g_Qsc[b] = vmax * (1.0f / 127.0f);
        s_qs = (vmax > 0.f) ? (127.0f / vmax) : 0.f;
    }
    __syncthreads();
    float qs = s_qs;
    char4 pk;
    pk.x = (char)__float2int_rn(nx * qs);
    pk.y = (char)__float2int_rn(ny * qs);
    pk.z = (char)__float2int_rn(nz * qs);
    pk.w = (char)__float2int_rn(nw * qs);
    reinterpret_cast<char4*>(g_Qs8)[(size_t)b * 256 + t] = pk;
}

// ---------------------------------------------------------------------------
// Kernel 2: per-row ||n|| -> quantized s8 N + scale
// ---------------------------------------------------------------------------
__global__ void k_norm_n(const float* __restrict__ n) {
    int b = blockIdx.x, t = threadIdx.x;
    float4 a = reinterpret_cast<const float4*>(n + (size_t)b * D_)[t];
    float nn = a.x*a.x + a.y*a.y + a.z*a.z + a.w*a.w;
    #pragma unroll
    for (int o = 16; o > 0; o >>= 1) nn += __shfl_xor_sync(0xffffffffu, nn, o);
    __shared__ float sn[8];
    __shared__ float s_inv, s_qs;
    int w = t >> 5, l = t & 31;
    if (l == 0) sn[w] = nn;
    __syncthreads();
    if (t == 0) {
        float NN = 0.f;
        #pragma unroll
        for (int i = 0; i < 8; i++) NN += sn[i];
        float qn = sqrtf(NN);
        s_inv = (qn > 0.f) ? (1.0f / qn) : 0.f;
    }
    __syncthreads();
    float inv = s_inv;
    float nx = a.x * inv, ny = a.y * inv, nz = a.z * inv, nw = a.w * inv;

    float m = fmaxf(fmaxf(fabsf(nx), fabsf(ny)), fmaxf(fabsf(nz), fabsf(nw)));
    #pragma unroll
    for (int o = 16; o > 0; o >>= 1) m = fmaxf(m, __shfl_xor_sync(0xffffffffu, m, o));
    if (l == 0) sn[w] = m;
    __syncthreads();
    if (t == 0) {
        float vmax = 0.f;
        #pragma unroll
        for (int i = 0; i < 8; i++) vmax = fmaxf(vmax, sn[i]);
        g_Nsc[b] = vmax * (1.0f / 127.0f);
        s_qs = (vmax > 0.f) ? (127.0f / vmax) : 0.f;
    }
    __syncthreads();
    float qs = s_qs;
    char4 pk;
    pk.x = (char)__float2int_rn(nx * qs);
    pk.y = (char)__float2int_rn(ny * qs);
    pk.z = (char)__float2int_rn(nz * qs);
    pk.w = (char)__float2int_rn(nw * qs);
    reinterpret_cast<char4*>(g_Ns8)[(size_t)b * 256 + t] = pk;
}

// ---------------------------------------------------------------------------
// poly exp on [-1.2, 1.2] (deg-9 Taylor, FMA pipe only)
// ---------------------------------------------------------------------------
__device__ __forceinline__ float poly_exp(float x) {
    float e = 2.7557319e-6f;
    e = fmaf(e, x, 2.4801587e-5f);
    e = fmaf(e, x, 1.9841270e-4f);
    e = fmaf(e, x, 1.3888889e-3f);
    e = fmaf(e, x, 8.3333333e-3f);
    e = fmaf(e, x, 4.1666668e-2f);
    e = fmaf(e, x, 1.6666667e-1f);
    e = fmaf(e, x, 0.5f);
    e = fmaf(e, x, 1.0f);
    e = fmaf(e, x, 1.0f);
    return e;
}

__device__ __forceinline__ void cpa16(uint32_t dst_smem, const void* src) {
    asm volatile("cp.async.cg.shared.global [%0], [%1], 16;" :: "r"(dst_smem), "l"(src));
}

#define LDSM4(r0, r1, r2, r3, addr) \
    asm volatile("ldmatrix.sync.aligned.m8n8.x4.shared.b16 {%0,%1,%2,%3}, [%4];" \
        : "=r"(r0), "=r"(r1), "=r"(r2), "=r"(r3) : "r"(addr))

#define MMA_S8(d, av, b0, b1) \
    asm volatile("mma.sync.aligned.m16n8k32.row.col.s32.s8.s8.s32 " \
        "{%0,%1,%2,%3}, {%4,%5,%6,%7}, {%8,%9}, {%0,%1,%2,%3};" \
        : "+r"((d)[0]), "+r"((d)[1]), "+r"((d)[2]), "+r"((d)[3]) \
        : "r"((av)[0]), "r"((av)[1]), "r"((av)[2]), "r"((av)[3]), "r"(b0), "r"(b1))

// ---------------------------------------------------------------------------
// Kernel 3: s8 mma.sync GEMM (native IMMA), 128x128 block tile, 32x32 warp
// tile (k32), 3-stage cp.async pipeline, register double-buffering, single
// barrier per K-iter, fused dequant + poly-exp + deterministic partials.
// grid = (NNEG/128, B_/128), block = 512 (16 warps as 4x4)
// ---------------------------------------------------------------------------
__global__ __launch_bounds__(512, 1) void k_gemm() {
    extern __shared__ __align__(16) char smem_raw[];
    int*   Ci  = reinterpret_cast<int*>(smem_raw);
    float* csm = reinterpret_cast<float*>(smem_raw + CS_OFF);
    const uint32_t sbase = (uint32_t)__cvta_generic_to_shared(smem_raw);

    const int t = threadIdx.x;
    const int warp = t >> 5, lane = t & 31;
    const int wm = warp >> 2;   // 0..3 : 32-row strip
    const int wn = warp & 3;    // 0..3 : 32-col strip
    const int bx = blockIdx.x, by = blockIdx.y;

    const int8_t* Aptr = g_Qs8 + (size_t)by * BM * D_;
    const int8_t* Bptr = g_Ns8 + (size_t)bx * BN * D_;

    // stage loader: 2048 16B chunks, 4/thread (i 0,1 = A rows; 2,3 = B rows)
    auto load_stage = [&](int slot, int k0) {
        uint32_t base = sbase + (uint32_t)slot * STAGE_B;
        #pragma unroll
        for (int i = 0; i < 2; i++) {
            int c = t + 512 * i;
            int r = c >> 3, c16 = c & 7;
            cpa16(base + (uint32_t)(r * LDK + c16 * 16),
                  Aptr + (size_t)r * D_ + k0 + c16 * 16);
        }
        #pragma unroll
        for (int i = 2; i < 4; i++) {
            int c = t + 512 * i;
            int r = c >> 3, c16 = c & 7;
            cpa16(base + (uint32_t)(r * LDK + c16 * 16),
                  Bptr + (size_t)(r - 128) * D_ + k0 + c16 * 16);
        }
        asm volatile("cp.async.commit_group;");
    };

    // ldmatrix per-thread address components (byte-identical to bf16 k16 case)
    const uint32_t lrow16 = (uint32_t)((lane & 7) | (((lane >> 3) & 1) << 3));
    const uint32_t lbyteA = (uint32_t)((lane >> 4) * 16);
    const int btile = lane >> 3, bnrow = lane & 7;

    uint32_t aoff[2], boff[2];
    #pragma unroll
    for (int s = 0; s < 2; s++)
        aoff[s] = (uint32_t)((wm * 32 + s * 16 + (int)lrow16) * LDK) + lbyteA;
    #pragma unroll
    for (int p = 0; p < 2; p++) {
        int strip = 2 * p + (btile >> 1);
        boff[p] = (uint32_t)(128 * LDK + (wn * 32 + strip * 8 + bnrow) * LDK
                             + (btile & 1) * 16);
    }

    uint32_t afr[2][2][4];
    uint32_t bfr[2][2][4];
    int acc[2][4][4] = {};   // [mi][nj][reg], s32

    auto load_frags = [&](uint32_t base, int kk, int buf) {
        uint32_t ko = (uint32_t)(kk * 32);   // 32 bytes = k32 s8
        #pragma unroll
        for (int s = 0; s < 2; s++)
            LDSM4(afr[buf][s][0], afr[buf][s][1], afr[buf][s][2], afr[buf][s][3],
                  base + aoff[s] + ko);
        #pragma unroll
        for (int p = 0; p < 2; p++)
            LDSM4(bfr[buf][p][0], bfr[buf][p][1], bfr[buf][p][2], bfr[buf][p][3],
                  base + boff[p] + ko);
    };

    load_stage(0, 0);
    load_stage(1, BKB);

    for (int it = 0; it < NIT; it++) {
        const int slot = it % 3;
        asm volatile("cp.async.wait_group 1;");
        __syncthreads();
        if (it + 2 < NIT) load_stage((it + 2) % 3, (it + 2) * BKB);
        else              asm volatile("cp.async.commit_group;");

        const uint32_t base = sbase + (uint32_t)slot * STAGE_B;
        load_frags(base, 0, 0);
        #pragma unroll
        for (int kk = 0; kk < 4; kk++) {
            const int cur = kk & 1;
            if (kk < 3) load_frags(base, kk + 1, cur ^ 1);
            #pragma unroll
            for (int mi = 0; mi < 2; mi++)
                #pragma unroll
                for (int nj = 0; nj < 4; nj++) {
                    const uint32_t* bp = &bfr[cur][nj >> 1][(nj & 1) * 2];
                    MMA_S8(acc[mi][nj], afr[cur][mi], bp[0], bp[1]);
                }
        }
    }
    __syncthreads();   // smem pipeline dead; reuse as C buffer

    // store s32 accumulators to smem C (m16n8 fragment layout)
    const int g = lane >> 2, tt = lane & 3;
    #pragma unroll
    for (int mi = 0; mi < 2; mi++)
        #pragma unroll
        for (int nj = 0; nj < 4; nj++) {
            int row0 = wm * 32 + mi * 16 + g;
            int col  = wn * 32 + nj * 8 + tt * 2;
            *reinterpret_cast<int2*>(&Ci[(size_t)row0 * EPI_LD + col]) =
                make_int2(acc[mi][nj][0], acc[mi][nj][1]);
            *reinterpret_cast<int2*>(&Ci[(size_t)(row0 + 8) * EPI_LD + col]) =
                make_int2(acc[mi][nj][2], acc[mi][nj][3]);
        }
    if (t < BN) csm[t] = g_Nsc[(size_t)bx * BN + t];
    __syncthreads();

    // fused dequant + exp + row partial sums: 4 threads per row, 32 cols each
    const int row = t >> 2, seg = t & 3;
    const float rsT = g_Qsc[(size_t)by * BM + row] * c_invT;
    const int* cr = &Ci[(size_t)row * EPI_LD + seg * 32];
    const float* cs = &csm[seg * 32];
    float s = 0.f;
    #pragma unroll
    for (int j = 0; j < 32; j++)
        s += poly_exp((float)cr[j] * rsT * cs[j]);
    s += __shfl_xor_sync(0xffffffffu, s, 1);
    s += __shfl_xor_sync(0xffffffffu, s, 2);
    if (seg == 0)
        g_part[(size_t)(by * BM + row) * NTILES + bx] = s;  // deterministic
}

// ---------------------------------------------------------------------------
// Kernel 4a: per-row loss term (8192 threads)
// ---------------------------------------------------------------------------
__global__ void k_rowloss() {
    int b = blockIdx.x * 256 + threadIdx.x;
    const float4* pr = reinterpret_cast<const float4*>(&g_part[(size_t)b * NTILES]);
    float s2s = 0.f;
    #pragma unroll
    for (int j = 0; j < NTILES / 4; j++) {
        float4 v = pr[j];
        s2s += v.x + v.y + v.z + v.w;
    }
    float s2 = s2s * (1.0f / (float)NNEG);
    float s1 = expf(g_pos[b] * c_invT);
    g_row[b] = log1pf(s2 / s1);
}

// ---------------------------------------------------------------------------
// Kernel 4b: final scalar reduce
// ---------------------------------------------------------------------------
__global__ void k_reduce(float* __restrict__ out) {
    int t = threadIdx.x;
    double acc = 0.0;
    #pragma unroll
    for (int j = 0; j < 32; j++)
        acc += (double)g_row[t + j * 256];
    #pragma unroll
    for (int o = 16; o > 0; o >>= 1) acc += __shfl_xor_sync(0xffffffffu, acc, o);
    __shared__ double sd[8];
    if ((t & 31) == 0) sd[t >> 5] = acc;
    __syncthreads();
    if (t == 0) {
        double tot = 0.0;
        #pragma unroll
        for (int i = 0; i < 8; i++) tot += sd[i];
        out[0] = (float)(tot / (double)B_);
    }
}

// ---------------------------------------------------------------------------
extern "C" void kernel_launch(void* const* d_in, const int* in_sizes, int n_in,
                              void* d_out, int out_size) {
    const float* q = (const float*)d_in[0];
    const float* p = (const float*)d_in[1];
    const float* n = (const float*)d_in[2];
    float* out = (float*)d_out;

    cudaFuncSetAttribute(k_gemm, cudaFuncAttributeMaxDynamicSharedMemorySize, SMEM_BYTES);

    k_norm_qp<<<B_, 256>>>(q, p);
    k_norm_n<<<NNEG, 256>>>(n);
    k_gemm<<<dim3(NNEG / BN, B_ / BM), 512, SMEM_BYTES>>>();
    k_rowloss<<<B_ / 256, 256>>>();
    k_reduce<<<1, 256>>>(out);
}

// round 13
// speedup vs baseline: 2.2103x; 2.2103x over previous
#include <cuda_runtime.h>
#include <cuda_bf16.h>
#include <cstdint>
#include <cstddef>

#define B_    8192
#define NNEG  8192
#define D_    1024

#define BM 128
#define BN 256
#define BK 64
#define NIT    (D_ / BK)     // 16
#define NTILES (NNEG / BN)   // 32

#define LDK 144              // smem row stride bytes (conflict-free ldmatrix)
#define STAGE_B (384 * LDK)  // A(128 rows)+B(256 rows) = 55296 B
#define NSTAGE 3
#define SMEM_BYTES (NSTAGE * STAGE_B)   // 165888
#define EPI_LD 260           // epilogue C row stride (floats)

__device__ __align__(16) __nv_bfloat16 g_Qh[(size_t)B_ * D_];
__device__ __align__(16) __nv_bfloat16 g_Nh[(size_t)NNEG * D_];
__device__ float g_pos[B_];
__device__ float g_part[(size_t)B_ * NTILES];
__device__ float g_row[B_];

__constant__ float c_invT = 1.0f / 0.92f;

// ---------------------------------------------------------------------------
// Kernel 1 (merged): blocks [0,8192) handle Q/P rows; [8192,16384) handle N
// ---------------------------------------------------------------------------
__global__ void k_norm(const float* __restrict__ q, const float* __restrict__ p,
                       const float* __restrict__ n) {
    int bid = blockIdx.x, t = threadIdx.x;
    __shared__ float sq[8], sp[8], sc[8];
    __shared__ float s_inv;
    int w = t >> 5, l = t & 31;

    if (bid < B_) {
        int b = bid;
        float4 a = reinterpret_cast<const float4*>(q + (size_t)b * D_)[t];
        float4 c = reinterpret_cast<const float4*>(p + (size_t)b * D_)[t];
        float qq = a.x*a.x + a.y*a.y + a.z*a.z + a.w*a.w;
        float pp = c.x*c.x + c.y*c.y + c.z*c.z + c.w*c.w;
        float qp = a.x*c.x + a.y*c.y + a.z*c.z + a.w*c.w;
        #pragma unroll
        for (int o = 16; o > 0; o >>= 1) {
            qq += __shfl_xor_sync(0xffffffffu, qq, o);
            pp += __shfl_xor_sync(0xffffffffu, pp, o);
            qp += __shfl_xor_sync(0xffffffffu, qp, o);
        }
        if (l == 0) { sq[w] = qq; sp[w] = pp; sc[w] = qp; }
        __syncthreads();
        if (t == 0) {
            float QQ = 0.f, PP = 0.f, QP = 0.f;
            #pragma unroll
            for (int i = 0; i < 8; i++) { QQ += sq[i]; PP += sp[i]; QP += sc[i]; }
            float qn = sqrtf(QQ), pn = sqrtf(PP);
            g_pos[b] = QP / fmaxf(qn * pn, 1e-6f);
            s_inv = (qn > 0.f) ? (1.0f / qn) : 0.f;
        }
        __syncthreads();
        float inv = s_inv;
        __nv_bfloat162 lo = __floats2bfloat162_rn(a.x * inv, a.y * inv);
        __nv_bfloat162 hi = __floats2bfloat162_rn(a.z * inv, a.w * inv);
        __nv_bfloat162* dst = reinterpret_cast<__nv_bfloat162*>(g_Qh) + (size_t)b * (D_ / 2) + t * 2;
        dst[0] = lo; dst[1] = hi;
    } else {
        int b = bid - B_;
        float4 a = reinterpret_cast<const float4*>(n + (size_t)b * D_)[t];
        float nn = a.x*a.x + a.y*a.y + a.z*a.z + a.w*a.w;
        #pragma unroll
        for (int o = 16; o > 0; o >>= 1) nn += __shfl_xor_sync(0xffffffffu, nn, o);
        if (l == 0) sq[w] = nn;
        __syncthreads();
        if (t == 0) {
            float NN = 0.f;
            #pragma unroll
            for (int i = 0; i < 8; i++) NN += sq[i];
            float qn = sqrtf(NN);
            s_inv = (qn > 0.f) ? (1.0f / qn) : 0.f;
        }
        __syncthreads();
        float inv = s_inv;
        __nv_bfloat162 lo = __floats2bfloat162_rn(a.x * inv, a.y * inv);
        __nv_bfloat162 hi = __floats2bfloat162_rn(a.z * inv, a.w * inv);
        __nv_bfloat162* dst = reinterpret_cast<__nv_bfloat162*>(g_Nh) + (size_t)b * (D_ / 2) + t * 2;
        dst[0] = lo; dst[1] = hi;
    }
}

// ---------------------------------------------------------------------------
// poly exp on [-1.2, 1.2] (deg-9 Taylor, FMA pipe only)
// ---------------------------------------------------------------------------
__device__ __forceinline__ float poly_exp(float x) {
    float e = 2.7557319e-6f;
    e = fmaf(e, x, 2.4801587e-5f);
    e = fmaf(e, x, 1.9841270e-4f);
    e = fmaf(e, x, 1.3888889e-3f);
    e = fmaf(e, x, 8.3333333e-3f);
    e = fmaf(e, x, 4.1666668e-2f);
    e = fmaf(e, x, 1.6666667e-1f);
    e = fmaf(e, x, 0.5f);
    e = fmaf(e, x, 1.0f);
    e = fmaf(e, x, 1.0f);
    return e;
}

__device__ __forceinline__ void cpa16(uint32_t dst_smem, const void* src) {
    asm volatile("cp.async.cg.shared.global [%0], [%1], 16;" :: "r"(dst_smem), "l"(src));
}

#define LDSM4(r0, r1, r2, r3, addr) \
    asm volatile("ldmatrix.sync.aligned.m8n8.x4.shared.b16 {%0,%1,%2,%3}, [%4];" \
        : "=r"(r0), "=r"(r1), "=r"(r2), "=r"(r3) : "r"(addr))

#define MMA_BF16(d, av, b0, b1) \
    asm volatile("mma.sync.aligned.m16n8k16.row.col.f32.bf16.bf16.f32 " \
        "{%0,%1,%2,%3}, {%4,%5,%6,%7}, {%8,%9}, {%0,%1,%2,%3};" \
        : "+f"((d)[0]), "+f"((d)[1]), "+f"((d)[2]), "+f"((d)[3]) \
        : "r"((av)[0]), "r"((av)[1]), "r"((av)[2]), "r"((av)[3]), "r"(b0), "r"(b1))

// ---------------------------------------------------------------------------
// Kernel 2: bf16 mma.sync GEMM, 128x256 block tile, 64x64 warp tile, BK=64,
// 3-stage cp.async pipeline, register double-buffering, one barrier/K-iter,
// fused poly-exp + deterministic row partials.
// grid = (NNEG/256, B_/128), block = 256 (8 warps as 2x4)
// ---------------------------------------------------------------------------
__global__ __launch_bounds__(256, 1) void k_gemm() {
    extern __shared__ __align__(16) char smem_raw[];
    float* Cf = reinterpret_cast<float*>(smem_raw);
    const uint32_t sbase = (uint32_t)__cvta_generic_to_shared(smem_raw);

    const int t = threadIdx.x;
    const int warp = t >> 5, lane = t & 31;
    const int wm = warp >> 2;   // 0..1 : 64-row strip
    const int wn = warp & 3;    // 0..3 : 64-col strip
    const int bx = blockIdx.x, by = blockIdx.y;

    const __nv_bfloat16* Aptr = g_Qh + (size_t)by * BM * D_;
    const __nv_bfloat16* Bptr = g_Nh + (size_t)bx * BN * D_;

    // stage loader: A = 1024 chunks (4/thread), B = 2048 chunks (8/thread)
    auto load_stage = [&](int slot, int k0) {
        uint32_t base = sbase + (uint32_t)slot * STAGE_B;
        #pragma unroll
        for (int i = 0; i < 4; i++) {
            int c = t + 256 * i;
            int r = c >> 3, c16 = c & 7;
            cpa16(base + (uint32_t)(r * LDK + c16 * 16),
                  Aptr + (size_t)r * D_ + k0 + c16 * 8);
        }
        #pragma unroll
        for (int i = 0; i < 8; i++) {
            int c = t + 256 * i;
            int r = c >> 3, c16 = c & 7;
            cpa16(base + (uint32_t)((128 + r) * LDK + c16 * 16),
                  Bptr + (size_t)r * D_ + k0 + c16 * 8);
        }
        asm volatile("cp.async.commit_group;");
    };

    // ldmatrix per-thread address components
    const uint32_t lrow16 = (uint32_t)((lane & 7) | (((lane >> 3) & 1) << 3)); // 0..15
    const uint32_t lbyteA = (uint32_t)((lane >> 4) * 16);                       // A k-half
    const int btile = lane >> 3, bnrow = lane & 7;

    uint32_t aoff[4], boff[4];
    #pragma unroll
    for (int s = 0; s < 4; s++)
        aoff[s] = (uint32_t)((wm * 64 + s * 16 + (int)lrow16) * LDK) + lbyteA;
    #pragma unroll
    for (int p = 0; p < 4; p++) {
        int strip = 2 * p + (btile >> 1);
        boff[p] = (uint32_t)((128 + wn * 64 + strip * 8 + bnrow) * LDK
                             + (btile & 1) * 16);
    }

    uint32_t afr[2][4][4];    // [buf][m16 strip][reg]
    uint32_t bfr[2][4][4];    // [buf][n16 pair][reg]
    float acc[4][8][4] = {};  // [mi][nj][reg]

    auto load_frags = [&](uint32_t base, int kk, int buf) {
        uint32_t ko = (uint32_t)(kk * 32);
        #pragma unroll
        for (int s = 0; s < 4; s++)
            LDSM4(afr[buf][s][0], afr[buf][s][1], afr[buf][s][2], afr[buf][s][3],
                  base + aoff[s] + ko);
        #pragma unroll
        for (int p = 0; p < 4; p++)
            LDSM4(bfr[buf][p][0], bfr[buf][p][1], bfr[buf][p][2], bfr[buf][p][3],
                  base + boff[p] + ko);
    };

    load_stage(0, 0);
    load_stage(1, BK);

    for (int it = 0; it < NIT; it++) {
        const int slot = it % 3;
        asm volatile("cp.async.wait_group 1;");
        __syncthreads();
        if (it + 2 < NIT) load_stage((it + 2) % 3, (it + 2) * BK);
        else              asm volatile("cp.async.commit_group;");

        const uint32_t base = sbase + (uint32_t)slot * STAGE_B;
        load_frags(base, 0, 0);
        #pragma unroll
        for (int kk = 0; kk < 4; kk++) {
            const int cur = kk & 1;
            if (kk < 3) load_frags(base, kk + 1, cur ^ 1);
            #pragma unroll
            for (int mi = 0; mi < 4; mi++)
                #pragma unroll
                for (int nj = 0; nj < 8; nj++) {
                    const uint32_t* bp = &bfr[cur][nj >> 1][(nj & 1) * 2];
                    MMA_BF16(acc[mi][nj], afr[cur][mi], bp[0], bp[1]);
                }
        }
    }
    __syncthreads();   // pipeline smem dead; reuse as C buffer

    // store accumulators to smem C (m16n8 fragment layout)
    const int g = lane >> 2, tt = lane & 3;
    #pragma unroll
    for (int mi = 0; mi < 4; mi++)
        #pragma unroll
        for (int nj = 0; nj < 8; nj++) {
            int row0 = wm * 64 + mi * 16 + g;
            int col  = wn * 64 + nj * 8 + tt * 2;
            *reinterpret_cast<float2*>(&Cf[(size_t)row0 * EPI_LD + col]) =
                make_float2(acc[mi][nj][0], acc[mi][nj][1]);
            *reinterpret_cast<float2*>(&Cf[(size_t)(row0 + 8) * EPI_LD + col]) =
                make_float2(acc[mi][nj][2], acc[mi][nj][3]);
        }
    __syncthreads();

    // fused exp + row partial sums: 2 threads per row, 128 cols each
    const int row = t >> 1, half = t & 1;
    const float4* cr = reinterpret_cast<const float4*>(&Cf[(size_t)row * EPI_LD + half * 128]);
    float s = 0.f;
    #pragma unroll 8
    for (int j = 0; j < 32; j++) {
        float4 v = cr[j];
        s += poly_exp(v.x * c_invT) + poly_exp(v.y * c_invT)
           + poly_exp(v.z * c_invT) + poly_exp(v.w * c_invT);
    }
    s += __shfl_xor_sync(0xffffffffu, s, 1);
    if (half == 0)
        g_part[(size_t)(by * BM + row) * NTILES + bx] = s;  // deterministic
}

// ---------------------------------------------------------------------------
// Kernel 3: per-row loss term (8192 threads)
// ---------------------------------------------------------------------------
__global__ void k_rowloss() {
    int b = blockIdx.x * 256 + threadIdx.x;
    const float4* pr = reinterpret_cast<const float4*>(&g_part[(size_t)b * NTILES]);
    float s2s = 0.f;
    #pragma unroll
    for (int j = 0; j < NTILES / 4; j++) {
        float4 v = pr[j];
        s2s += v.x + v.y + v.z + v.w;
    }
    float s2 = s2s * (1.0f / (float)NNEG);
    float s1 = expf(g_pos[b] * c_invT);
    g_row[b] = log1pf(s2 / s1);
}

// ---------------------------------------------------------------------------
// Kernel 4: final scalar reduce
// ---------------------------------------------------------------------------
__global__ void k_reduce(float* __restrict__ out) {
    int t = threadIdx.x;
    double acc = 0.0;
    #pragma unroll
    for (int j = 0; j < 32; j++)
        acc += (double)g_row[t + j * 256];
    #pragma unroll
    for (int o = 16; o > 0; o >>= 1) acc += __shfl_xor_sync(0xffffffffu, acc, o);
    __shared__ double sd[8];
    if ((t & 31) == 0) sd[t >> 5] = acc;
    __syncthreads();
    if (t == 0) {
        double tot = 0.0;
        #pragma unroll
        for (int i = 0; i < 8; i++) tot += sd[i];
        out[0] = (float)(tot / (double)B_);
    }
}

// ---------------------------------------------------------------------------
extern "C" void kernel_launch(void* const* d_in, const int* in_sizes, int n_in,
                              void* d_out, int out_size) {
    const float* q = (const float*)d_in[0];
    const float* p = (const float*)d_in[1];
    const float* n = (const float*)d_in[2];
    float* out = (float*)d_out;

    cudaFuncSetAttribute(k_gemm, cudaFuncAttributeMaxDynamicSharedMemorySize, SMEM_BYTES);

    k_norm<<<B_ + NNEG, 256>>>(q, p, n);
    k_gemm<<<dim3(NNEG / BN, B_ / BM), 256, SMEM_BYTES>>>();
    k_rowloss<<<B_ / 256, 256>>>();
    k_reduce<<<1, 256>>>(out);
}

// round 14
// speedup vs baseline: 2.3136x; 1.0467x over previous
#include <cuda_runtime.h>
#include <cuda_fp16.h>
#include <cstdint>
#include <cstddef>

#define B_    8192
#define NNEG  8192
#define D_    1024

#define BM 128
#define BN 128
#define BK 64
#define NIT    (D_ / BK)     // 16
#define NTILES (NNEG / BN)   // 64

#define LDK 144              // smem row stride bytes (conflict-free ldmatrix)
#define STAGE_B (256 * LDK)  // A(128 rows)+B(128 rows) = 36864 B
#define NSTAGE 3
#define SMEM_BYTES (NSTAGE * STAGE_B)   // 110592
#define EPI_LD 132

__device__ __align__(16) __half g_Qh[(size_t)B_ * D_];
__device__ __align__(16) __half g_Nh[(size_t)NNEG * D_];
__device__ float g_pos[B_];
__device__ float g_part[(size_t)B_ * NTILES];
__device__ float g_row[B_];

__constant__ float c_invT = 1.0f / 0.92f;

// ---------------------------------------------------------------------------
// Kernel 1 (merged): blocks [0,8192) do Q/P rows; [8192,16384) do N rows
// ---------------------------------------------------------------------------
__global__ void k_norm(const float* __restrict__ q, const float* __restrict__ p,
                       const float* __restrict__ n) {
    int bid = blockIdx.x, t = threadIdx.x;
    __shared__ float sq[8], sp[8], sc[8];
    __shared__ float s_inv;
    int w = t >> 5, l = t & 31;

    if (bid < B_) {
        int b = bid;
        float4 a = reinterpret_cast<const float4*>(q + (size_t)b * D_)[t];
        float4 c = reinterpret_cast<const float4*>(p + (size_t)b * D_)[t];
        float qq = a.x*a.x + a.y*a.y + a.z*a.z + a.w*a.w;
        float pp = c.x*c.x + c.y*c.y + c.z*c.z + c.w*c.w;
        float qp = a.x*c.x + a.y*c.y + a.z*c.z + a.w*c.w;
        #pragma unroll
        for (int o = 16; o > 0; o >>= 1) {
            qq += __shfl_xor_sync(0xffffffffu, qq, o);
            pp += __shfl_xor_sync(0xffffffffu, pp, o);
            qp += __shfl_xor_sync(0xffffffffu, qp, o);
        }
        if (l == 0) { sq[w] = qq; sp[w] = pp; sc[w] = qp; }
        __syncthreads();
        if (t == 0) {
            float QQ = 0.f, PP = 0.f, QP = 0.f;
            #pragma unroll
            for (int i = 0; i < 8; i++) { QQ += sq[i]; PP += sp[i]; QP += sc[i]; }
            float qn = sqrtf(QQ), pn = sqrtf(PP);
            g_pos[b] = QP / fmaxf(qn * pn, 1e-6f);
            s_inv = (qn > 0.f) ? (1.0f / qn) : 0.f;
        }
        __syncthreads();
        float inv = s_inv;
        __half2 lo = __floats2half2_rn(a.x * inv, a.y * inv);
        __half2 hi = __floats2half2_rn(a.z * inv, a.w * inv);
        __half2* dst = reinterpret_cast<__half2*>(g_Qh) + (size_t)b * (D_ / 2) + t * 2;
        dst[0] = lo; dst[1] = hi;
    } else {
        int b = bid - B_;
        float4 a = reinterpret_cast<const float4*>(n + (size_t)b * D_)[t];
        float nn = a.x*a.x + a.y*a.y + a.z*a.z + a.w*a.w;
        #pragma unroll
        for (int o = 16; o > 0; o >>= 1) nn += __shfl_xor_sync(0xffffffffu, nn, o);
        if (l == 0) sq[w] = nn;
        __syncthreads();
        if (t == 0) {
            float NN = 0.f;
            #pragma unroll
            for (int i = 0; i < 8; i++) NN += sq[i];
            float qn = sqrtf(NN);
            s_inv = (qn > 0.f) ? (1.0f / qn) : 0.f;
        }
        __syncthreads();
        float inv = s_inv;
        __half2 lo = __floats2half2_rn(a.x * inv, a.y * inv);
        __half2 hi = __floats2half2_rn(a.z * inv, a.w * inv);
        __half2* dst = reinterpret_cast<__half2*>(g_Nh) + (size_t)b * (D_ / 2) + t * 2;
        dst[0] = lo; dst[1] = hi;
    }
}

// ---------------------------------------------------------------------------
// poly exp on [-1.2, 1.2] (deg-9 Taylor, FMA pipe only)
// ---------------------------------------------------------------------------
__device__ __forceinline__ float poly_exp(float x) {
    float e = 2.7557319e-6f;
    e = fmaf(e, x, 2.4801587e-5f);
    e = fmaf(e, x, 1.9841270e-4f);
    e = fmaf(e, x, 1.3888889e-3f);
    e = fmaf(e, x, 8.3333333e-3f);
    e = fmaf(e, x, 4.1666668e-2f);
    e = fmaf(e, x, 1.6666667e-1f);
    e = fmaf(e, x, 0.5f);
    e = fmaf(e, x, 1.0f);
    e = fmaf(e, x, 1.0f);
    return e;
}

__device__ __forceinline__ void cpa16(uint32_t dst_smem, const void* src) {
    asm volatile("cp.async.cg.shared.global [%0], [%1], 16;" :: "r"(dst_smem), "l"(src));
}

#define LDSM4(r0, r1, r2, r3, addr) \
    asm volatile("ldmatrix.sync.aligned.m8n8.x4.shared.b16 {%0,%1,%2,%3}, [%4];" \
        : "=r"(r0), "=r"(r1), "=r"(r2), "=r"(r3) : "r"(addr))

// fp16 accumulate: D (2 regs, 4 halves) = A (4 regs) * B (2 regs) + D
#define MMA_F16ACC(d, av, b0, b1) \
    asm volatile("mma.sync.aligned.m16n8k16.row.col.f16.f16.f16.f16 " \
        "{%0,%1}, {%2,%3,%4,%5}, {%6,%7}, {%0,%1};" \
        : "+r"((d)[0]), "+r"((d)[1]) \
        : "r"((av)[0]), "r"((av)[1]), "r"((av)[2]), "r"((av)[3]), "r"(b0), "r"(b1))

// ---------------------------------------------------------------------------
// Kernel 2: fp16 mma.sync GEMM (fp16 accumulate), 128x128 block tile,
// 32x32 warp tile, BK=64, 3-stage cp.async pipeline, register
// double-buffering, one barrier/K-iter, fused poly-exp + row partials.
// grid = (NNEG/128, B_/128), block = 512 (16 warps as 4x4)
// ---------------------------------------------------------------------------
__global__ __launch_bounds__(512, 1) void k_gemm() {
    extern __shared__ __align__(16) char smem_raw[];
    float* Cf = reinterpret_cast<float*>(smem_raw);
    const uint32_t sbase = (uint32_t)__cvta_generic_to_shared(smem_raw);

    const int t = threadIdx.x;
    const int warp = t >> 5, lane = t & 31;
    const int wm = warp >> 2;   // 0..3 : 32-row strip
    const int wn = warp & 3;    // 0..3 : 32-col strip
    const int bx = blockIdx.x, by = blockIdx.y;

    const __half* Aptr = g_Qh + (size_t)by * BM * D_;
    const __half* Bptr = g_Nh + (size_t)bx * BN * D_;

    // stage loader: 2048 16B chunks, 4/thread (i 0,1 = A; 2,3 = B)
    auto load_stage = [&](int slot, int k0) {
        uint32_t base = sbase + (uint32_t)slot * STAGE_B;
        #pragma unroll
        for (int i = 0; i < 2; i++) {
            int c = t + 512 * i;
            int r = c >> 3, c16 = c & 7;
            cpa16(base + (uint32_t)(r * LDK + c16 * 16),
                  Aptr + (size_t)r * D_ + k0 + c16 * 8);
        }
        #pragma unroll
        for (int i = 2; i < 4; i++) {
            int c = t + 512 * i;
            int r = c >> 3, c16 = c & 7;
            cpa16(base + (uint32_t)(r * LDK + c16 * 16),
                  Bptr + (size_t)(r - 128) * D_ + k0 + c16 * 8);
        }
        asm volatile("cp.async.commit_group;");
    };

    // ldmatrix per-thread address components
    const uint32_t lrow16 = (uint32_t)((lane & 7) | (((lane >> 3) & 1) << 3)); // 0..15
    const uint32_t lbyteA = (uint32_t)((lane >> 4) * 16);                       // A k-half
    const int btile = lane >> 3, bnrow = lane & 7;

    uint32_t aoff[2], boff[2];
    #pragma unroll
    for (int s = 0; s < 2; s++)
        aoff[s] = (uint32_t)((wm * 32 + s * 16 + (int)lrow16) * LDK) + lbyteA;
    #pragma unroll
    for (int p = 0; p < 2; p++) {
        int strip = 2 * p + (btile >> 1);
        boff[p] = (uint32_t)(128 * LDK + (wn * 32 + strip * 8 + bnrow) * LDK
                             + (btile & 1) * 16);
    }

    uint32_t afr[2][2][4];       // [buf][strip][reg]
    uint32_t bfr[2][2][4];       // [buf][pair][reg]
    uint32_t acc[2][4][2] = {};  // [mi][nj][reg] -- packed half2, zero-init

    auto load_frags = [&](uint32_t base, int kk, int buf) {
        uint32_t ko = (uint32_t)(kk * 32);
        #pragma unroll
        for (int s = 0; s < 2; s++)
            LDSM4(afr[buf][s][0], afr[buf][s][1], afr[buf][s][2], afr[buf][s][3],
                  base + aoff[s] + ko);
        #pragma unroll
        for (int p = 0; p < 2; p++)
            LDSM4(bfr[buf][p][0], bfr[buf][p][1], bfr[buf][p][2], bfr[buf][p][3],
                  base + boff[p] + ko);
    };

    load_stage(0, 0);
    load_stage(1, BK);

    for (int it = 0; it < NIT; it++) {
        const int slot = it % 3;
        asm volatile("cp.async.wait_group 1;");
        __syncthreads();
        if (it + 2 < NIT) load_stage((it + 2) % 3, (it + 2) * BK);
        else              asm volatile("cp.async.commit_group;");

        const uint32_t base = sbase + (uint32_t)slot * STAGE_B;
        load_frags(base, 0, 0);
        #pragma unroll
        for (int kk = 0; kk < 4; kk++) {
            const int cur = kk & 1;
            if (kk < 3) load_frags(base, kk + 1, cur ^ 1);
            #pragma unroll
            for (int mi = 0; mi < 2; mi++)
                #pragma unroll
                for (int nj = 0; nj < 4; nj++) {
                    const uint32_t* bp = &bfr[cur][nj >> 1][(nj & 1) * 2];
                    MMA_F16ACC(acc[mi][nj], afr[cur][mi], bp[0], bp[1]);
                }
        }
    }
    __syncthreads();   // pipeline smem dead; reuse as C buffer

    // store accumulators (half2 -> float) to smem C
    const int g = lane >> 2, tt = lane & 3;
    #pragma unroll
    for (int mi = 0; mi < 2; mi++)
        #pragma unroll
        for (int nj = 0; nj < 4; nj++) {
            int row0 = wm * 32 + mi * 16 + g;
            int col  = wn * 32 + nj * 8 + tt * 2;
            float2 v01 = __half22float2(*reinterpret_cast<__half2*>(&acc[mi][nj][0]));
            float2 v23 = __half22float2(*reinterpret_cast<__half2*>(&acc[mi][nj][1]));
            *reinterpret_cast<float2*>(&Cf[(size_t)row0 * EPI_LD + col]) = v01;
            *reinterpret_cast<float2*>(&Cf[(size_t)(row0 + 8) * EPI_LD + col]) = v23;
        }
    __syncthreads();

    // fused exp + row partial sums: 4 threads per row, 32 cols each
    const int row = t >> 2, seg = t & 3;
    const float* cr = &Cf[(size_t)row * EPI_LD + seg * 32];
    float s = 0.f;
    #pragma unroll
    for (int j = 0; j < 32; j++)
        s += poly_exp(cr[j] * c_invT);
    s += __shfl_xor_sync(0xffffffffu, s, 1);
    s += __shfl_xor_sync(0xffffffffu, s, 2);
    if (seg == 0)
        g_part[(size_t)(by * BM + row) * NTILES + bx] = s;  // deterministic
}

// ---------------------------------------------------------------------------
// Kernel 3: per-row loss term (8192 threads)
// ---------------------------------------------------------------------------
__global__ void k_rowloss() {
    int b = blockIdx.x * 256 + threadIdx.x;
    const float4* pr = reinterpret_cast<const float4*>(&g_part[(size_t)b * NTILES]);
    float s2s = 0.f;
    #pragma unroll
    for (int j = 0; j < NTILES / 4; j++) {
        float4 v = pr[j];
        s2s += v.x + v.y + v.z + v.w;
    }
    float s2 = s2s * (1.0f / (float)NNEG);
    float s1 = expf(g_pos[b] * c_invT);
    g_row[b] = log1pf(s2 / s1);
}

// ---------------------------------------------------------------------------
// Kernel 4: final scalar reduce
// ---------------------------------------------------------------------------
__global__ void k_reduce(float* __restrict__ out) {
    int t = threadIdx.x;
    double acc = 0.0;
    #pragma unroll
    for (int j = 0; j < 32; j++)
        acc += (double)g_row[t + j * 256];
    #pragma unroll
    for (int o = 16; o > 0; o >>= 1) acc += __shfl_xor_sync(0xffffffffu, acc, o);
    __shared__ double sd[8];
    if ((t & 31) == 0) sd[t >> 5] = acc;
    __syncthreads();
    if (t == 0) {
        double tot = 0.0;
        #pragma unroll
        for (int i = 0; i < 8; i++) tot += sd[i];
        out[0] = (float)(tot / (double)B_);
    }
}

// ---------------------------------------------------------------------------
extern "C" void kernel_launch(void* const* d_in, const int* in_sizes, int n_in,
                              void* d_out, int out_size) {
    const float* q = (const float*)d_in[0];
    const float* p = (const float*)d_in[1];
    const float* n = (const float*)d_in[2];
    float* out = (float*)d_out;

    cudaFuncSetAttribute(k_gemm, cudaFuncAttributeMaxDynamicSharedMemorySize, SMEM_BYTES);

    k_norm<<<B_ + NNEG, 256>>>(q, p, n);
    k_gemm<<<dim3(NNEG / BN, B_ / BM), 512, SMEM_BYTES>>>();
    k_rowloss<<<B_ / 256, 256>>>();
    k_reduce<<<1, 256>>>(out);
}

// round 15
// speedup vs baseline: 2.3173x; 1.0016x over previous
#include <cuda_runtime.h>
#include <cuda_fp16.h>
#include <cstdint>
#include <cstddef>

#define B_    8192
#define NNEG  8192
#define D_    1024

#define BM 128
#define BN 128
#define BK 64
#define NIT    (D_ / BK)     // 16
#define NTILES (NNEG / BN)   // 64

#define LDK 144              // smem row stride bytes (conflict-free ldmatrix)
#define STAGE_B (256 * LDK)  // A(128 rows)+B(128 rows) = 36864 B
#define NSTAGE 2
#define SMEM_BYTES (NSTAGE * STAGE_B)   // 73728
#define EPI_LD 132           // 128*132*4 = 67584 <= 73728

__device__ __align__(16) __half g_Qh[(size_t)B_ * D_];
__device__ __align__(16) __half g_Nh[(size_t)NNEG * D_];
__device__ float g_pos[B_];
__device__ float g_part[(size_t)B_ * NTILES];
__device__ float g_row[B_];

__constant__ float c_invT = 1.0f / 0.92f;

// ---------------------------------------------------------------------------
// Kernel 1 (merged): blocks [0,8192) do Q/P rows; [8192,16384) do N rows
// ---------------------------------------------------------------------------
__global__ void k_norm(const float* __restrict__ q, const float* __restrict__ p,
                       const float* __restrict__ n) {
    int bid = blockIdx.x, t = threadIdx.x;
    __shared__ float sq[8], sp[8], sc[8];
    __shared__ float s_inv;
    int w = t >> 5, l = t & 31;

    if (bid < B_) {
        int b = bid;
        float4 a = reinterpret_cast<const float4*>(q + (size_t)b * D_)[t];
        float4 c = reinterpret_cast<const float4*>(p + (size_t)b * D_)[t];
        float qq = a.x*a.x + a.y*a.y + a.z*a.z + a.w*a.w;
        float pp = c.x*c.x + c.y*c.y + c.z*c.z + c.w*c.w;
        float qp = a.x*c.x + a.y*c.y + a.z*c.z + a.w*c.w;
        #pragma unroll
        for (int o = 16; o > 0; o >>= 1) {
            qq += __shfl_xor_sync(0xffffffffu, qq, o);
            pp += __shfl_xor_sync(0xffffffffu, pp, o);
            qp += __shfl_xor_sync(0xffffffffu, qp, o);
        }
        if (l == 0) { sq[w] = qq; sp[w] = pp; sc[w] = qp; }
        __syncthreads();
        if (t == 0) {
            float QQ = 0.f, PP = 0.f, QP = 0.f;
            #pragma unroll
            for (int i = 0; i < 8; i++) { QQ += sq[i]; PP += sp[i]; QP += sc[i]; }
            float qn = sqrtf(QQ), pn = sqrtf(PP);
            g_pos[b] = QP / fmaxf(qn * pn, 1e-6f);
            s_inv = (qn > 0.f) ? (1.0f / qn) : 0.f;
        }
        __syncthreads();
        float inv = s_inv;
        __half2 lo = __floats2half2_rn(a.x * inv, a.y * inv);
        __half2 hi = __floats2half2_rn(a.z * inv, a.w * inv);
        __half2* dst = reinterpret_cast<__half2*>(g_Qh) + (size_t)b * (D_ / 2) + t * 2;
        dst[0] = lo; dst[1] = hi;
    } else {
        int b = bid - B_;
        float4 a = reinterpret_cast<const float4*>(n + (size_t)b * D_)[t];
        float nn = a.x*a.x + a.y*a.y + a.z*a.z + a.w*a.w;
        #pragma unroll
        for (int o = 16; o > 0; o >>= 1) nn += __shfl_xor_sync(0xffffffffu, nn, o);
        if (l == 0) sq[w] = nn;
        __syncthreads();
        if (t == 0) {
            float NN = 0.f;
            #pragma unroll
            for (int i = 0; i < 8; i++) NN += sq[i];
            float qn = sqrtf(NN);
            s_inv = (qn > 0.f) ? (1.0f / qn) : 0.f;
        }
        __syncthreads();
        float inv = s_inv;
        __half2 lo = __floats2half2_rn(a.x * inv, a.y * inv);
        __half2 hi = __floats2half2_rn(a.z * inv, a.w * inv);
        __half2* dst = reinterpret_cast<__half2*>(g_Nh) + (size_t)b * (D_ / 2) + t * 2;
        dst[0] = lo; dst[1] = hi;
    }
}

// ---------------------------------------------------------------------------
// poly exp on [-1.2, 1.2] (deg-9 Taylor, FMA pipe only)
// ---------------------------------------------------------------------------
__device__ __forceinline__ float poly_exp(float x) {
    float e = 2.7557319e-6f;
    e = fmaf(e, x, 2.4801587e-5f);
    e = fmaf(e, x, 1.9841270e-4f);
    e = fmaf(e, x, 1.3888889e-3f);
    e = fmaf(e, x, 8.3333333e-3f);
    e = fmaf(e, x, 4.1666668e-2f);
    e = fmaf(e, x, 1.6666667e-1f);
    e = fmaf(e, x, 0.5f);
    e = fmaf(e, x, 1.0f);
    e = fmaf(e, x, 1.0f);
    return e;
}

__device__ __forceinline__ void cpa16(uint32_t dst_smem, const void* src) {
    asm volatile("cp.async.cg.shared.global [%0], [%1], 16;" :: "r"(dst_smem), "l"(src));
}

#define LDSM4(r0, r1, r2, r3, addr) \
    asm volatile("ldmatrix.sync.aligned.m8n8.x4.shared.b16 {%0,%1,%2,%3}, [%4];" \
        : "=r"(r0), "=r"(r1), "=r"(r2), "=r"(r3) : "r"(addr))

// fp16 accumulate: D (2 regs, 4 halves) = A (4 regs) * B (2 regs) + D
#define MMA_F16ACC(d, av, b0, b1) \
    asm volatile("mma.sync.aligned.m16n8k16.row.col.f16.f16.f16.f16 " \
        "{%0,%1}, {%2,%3,%4,%5}, {%6,%7}, {%0,%1};" \
        : "+r"((d)[0]), "+r"((d)[1]) \
        : "r"((av)[0]), "r"((av)[1]), "r"((av)[2]), "r"((av)[3]), "r"(b0), "r"(b1))

// ---------------------------------------------------------------------------
// Kernel 2: fp16 mma.sync GEMM (fp16 accumulate), 128x128 block tile,
// 32x32 warp tile, BK=64, 2-stage cp.async pipeline, 2 CTAs/SM for
// cross-CTA overlap of fill/drain/epilogue with mainloop.
// grid = (NNEG/128, B_/128), block = 512 (16 warps as 4x4)
// ---------------------------------------------------------------------------
__global__ __launch_bounds__(512, 2) void k_gemm() {
    extern __shared__ __align__(16) char smem_raw[];
    float* Cf = reinterpret_cast<float*>(smem_raw);
    const uint32_t sbase = (uint32_t)__cvta_generic_to_shared(smem_raw);

    const int t = threadIdx.x;
    const int warp = t >> 5, lane = t & 31;
    const int wm = warp >> 2;   // 0..3 : 32-row strip
    const int wn = warp & 3;    // 0..3 : 32-col strip
    const int bx = blockIdx.x, by = blockIdx.y;

    const __half* Aptr = g_Qh + (size_t)by * BM * D_;
    const __half* Bptr = g_Nh + (size_t)bx * BN * D_;

    // stage loader: 2048 16B chunks, 4/thread (i 0,1 = A; 2,3 = B)
    auto load_stage = [&](int slot, int k0) {
        uint32_t base = sbase + (uint32_t)slot * STAGE_B;
        #pragma unroll
        for (int i = 0; i < 2; i++) {
            int c = t + 512 * i;
            int r = c >> 3, c16 = c & 7;
            cpa16(base + (uint32_t)(r * LDK + c16 * 16),
                  Aptr + (size_t)r * D_ + k0 + c16 * 8);
        }
        #pragma unroll
        for (int i = 2; i < 4; i++) {
            int c = t + 512 * i;
            int r = c >> 3, c16 = c & 7;
            cpa16(base + (uint32_t)(r * LDK + c16 * 16),
                  Bptr + (size_t)(r - 128) * D_ + k0 + c16 * 8);
        }
    };

    // ldmatrix per-thread address components
    const uint32_t lrow16 = (uint32_t)((lane & 7) | (((lane >> 3) & 1) << 3)); // 0..15
    const uint32_t lbyteA = (uint32_t)((lane >> 4) * 16);                       // A k-half
    const int btile = lane >> 3, bnrow = lane & 7;

    uint32_t aoff[2], boff[2];
    #pragma unroll
    for (int s = 0; s < 2; s++)
        aoff[s] = (uint32_t)((wm * 32 + s * 16 + (int)lrow16) * LDK) + lbyteA;
    #pragma unroll
    for (int p = 0; p < 2; p++) {
        int strip = 2 * p + (btile >> 1);
        boff[p] = (uint32_t)(128 * LDK + (wn * 32 + strip * 8 + bnrow) * LDK
                             + (btile & 1) * 16);
    }

    uint32_t afr[2][4];          // [strip][reg]  (single-buffered)
    uint32_t bfr[2][4];          // [pair][reg]
    uint32_t acc[2][4][2] = {};  // [mi][nj][reg] -- packed half2

    load_stage(0, 0);
    asm volatile("cp.async.commit_group;");

    for (int it = 0; it < NIT; it++) {
        const int cur = it & 1;
        if (it + 1 < NIT) load_stage(cur ^ 1, (it + 1) * BK);
        asm volatile("cp.async.commit_group;");
        asm volatile("cp.async.wait_group 1;");
        __syncthreads();

        const uint32_t base = sbase + (uint32_t)cur * STAGE_B;
        #pragma unroll
        for (int kk = 0; kk < 4; kk++) {
            uint32_t ko = (uint32_t)(kk * 32);
            #pragma unroll
            for (int s = 0; s < 2; s++)
                LDSM4(afr[s][0], afr[s][1], afr[s][2], afr[s][3],
                      base + aoff[s] + ko);
            #pragma unroll
            for (int p = 0; p < 2; p++)
                LDSM4(bfr[p][0], bfr[p][1], bfr[p][2], bfr[p][3],
                      base + boff[p] + ko);
            #pragma unroll
            for (int mi = 0; mi < 2; mi++)
                #pragma unroll
                for (int nj = 0; nj < 4; nj++) {
                    const uint32_t* bp = &bfr[nj >> 1][(nj & 1) * 2];
                    MMA_F16ACC(acc[mi][nj], afr[mi], bp[0], bp[1]);
                }
        }
        __syncthreads();
    }

    // store accumulators (half2 -> float) to smem C (pipeline smem is dead)
    const int g = lane >> 2, tt = lane & 3;
    #pragma unroll
    for (int mi = 0; mi < 2; mi++)
        #pragma unroll
        for (int nj = 0; nj < 4; nj++) {
            int row0 = wm * 32 + mi * 16 + g;
            int col  = wn * 32 + nj * 8 + tt * 2;
            float2 v01 = __half22float2(*reinterpret_cast<__half2*>(&acc[mi][nj][0]));
            float2 v23 = __half22float2(*reinterpret_cast<__half2*>(&acc[mi][nj][1]));
            *reinterpret_cast<float2*>(&Cf[(size_t)row0 * EPI_LD + col]) = v01;
            *reinterpret_cast<float2*>(&Cf[(size_t)(row0 + 8) * EPI_LD + col]) = v23;
        }
    __syncthreads();

    // fused exp + row partial sums: 4 threads per row, 32 cols each
    const int row = t >> 2, seg = t & 3;
    const float* cr = &Cf[(size_t)row * EPI_LD + seg * 32];
    float s = 0.f;
    #pragma unroll
    for (int j = 0; j < 32; j++)
        s += poly_exp(cr[j] * c_invT);
    s += __shfl_xor_sync(0xffffffffu, s, 1);
    s += __shfl_xor_sync(0xffffffffu, s, 2);
    if (seg == 0)
        g_part[(size_t)(by * BM + row) * NTILES + bx] = s;  // deterministic
}

// ---------------------------------------------------------------------------
// Kernel 3: per-row loss term (8192 threads)
// ---------------------------------------------------------------------------
__global__ void k_rowloss() {
    int b = blockIdx.x * 256 + threadIdx.x;
    const float4* pr = reinterpret_cast<const float4*>(&g_part[(size_t)b * NTILES]);
    float s2s = 0.f;
    #pragma unroll
    for (int j = 0; j < NTILES / 4; j++) {
        float4 v = pr[j];
        s2s += v.x + v.y + v.z + v.w;
    }
    float s2 = s2s * (1.0f / (float)NNEG);
    float s1 = expf(g_pos[b] * c_invT);
    g_row[b] = log1pf(s2 / s1);
}

// ---------------------------------------------------------------------------
// Kernel 4: final scalar reduce
// ---------------------------------------------------------------------------
__global__ void k_reduce(float* __restrict__ out) {
    int t = threadIdx.x;
    double acc = 0.0;
    #pragma unroll
    for (int j = 0; j < 32; j++)
        acc += (double)g_row[t + j * 256];
    #pragma unroll
    for (int o = 16; o > 0; o >>= 1) acc += __shfl_xor_sync(0xffffffffu, acc, o);
    __shared__ double sd[8];
    if ((t & 31) == 0) sd[t >> 5] = acc;
    __syncthreads();
    if (t == 0) {
        double tot = 0.0;
        #pragma unroll
        for (int i = 0; i < 8; i++) tot += sd[i];
        out[0] = (float)(tot / (double)B_);
    }
}

// ---------------------------------------------------------------------------
extern "C" void kernel_launch(void* const* d_in, const int* in_sizes, int n_in,
                              void* d_out, int out_size) {
    const float* q = (const float*)d_in[0];
    const float* p = (const float*)d_in[1];
    const float* n = (const float*)d_in[2];
    float* out = (float*)d_out;

    cudaFuncSetAttribute(k_gemm, cudaFuncAttributeMaxDynamicSharedMemorySize, SMEM_BYTES);

    k_norm<<<B_ + NNEG, 256>>>(q, p, n);
    k_gemm<<<dim3(NNEG / BN, B_ / BM), 512, SMEM_BYTES>>>();
    k_rowloss<<<B_ / 256, 256>>>();
    k_reduce<<<1, 256>>>(out);
}

// round 16
// speedup vs baseline: 2.3394x; 1.0095x over previous
#include <cuda_runtime.h>
#include <cuda_fp16.h>
#include <cstdint>
#include <cstddef>

#define B_    8192
#define NNEG  8192
#define D_    1024

#define BM 128
#define BN 128
#define BK 64
#define NIT    (D_ / BK)     // 16
#define NTILES (NNEG / BN)   // 64

#define LDK 144              // smem row stride bytes (conflict-free ldmatrix)
#define STAGE_B (256 * LDK)  // A(128 rows)+B(128 rows) = 36864 B
#define NSTAGE 2
#define SMEM_BYTES (NSTAGE * STAGE_B)   // 73728
#define EPI_LD 132           // 128*132*4 = 67584 <= 73728

#define NLBLK (B_ / 256)     // 32 loss blocks

__device__ __align__(16) __half g_Qh[(size_t)B_ * D_];
__device__ __align__(16) __half g_Nh[(size_t)NNEG * D_];
__device__ float g_pos[B_];
__device__ float g_part[(size_t)B_ * NTILES];
__device__ double g_blk[NLBLK];
__device__ unsigned int g_sem;   // zero-initialized; self-resetting ticket

__constant__ float c_invT = 1.0f / 0.92f;

// ---------------------------------------------------------------------------
// Kernel 1 (merged): blocks [0,8192) do Q/P rows; [8192,16384) do N rows
// ---------------------------------------------------------------------------
__global__ void k_norm(const float* __restrict__ q, const float* __restrict__ p,
                       const float* __restrict__ n) {
    int bid = blockIdx.x, t = threadIdx.x;
    __shared__ float sq[8], sp[8], sc[8];
    __shared__ float s_inv;
    int w = t >> 5, l = t & 31;

    if (bid < B_) {
        int b = bid;
        float4 a = reinterpret_cast<const float4*>(q + (size_t)b * D_)[t];
        float4 c = reinterpret_cast<const float4*>(p + (size_t)b * D_)[t];
        float qq = a.x*a.x + a.y*a.y + a.z*a.z + a.w*a.w;
        float pp = c.x*c.x + c.y*c.y + c.z*c.z + c.w*c.w;
        float qp = a.x*c.x + a.y*c.y + a.z*c.z + a.w*c.w;
        #pragma unroll
        for (int o = 16; o > 0; o >>= 1) {
            qq += __shfl_xor_sync(0xffffffffu, qq, o);
            pp += __shfl_xor_sync(0xffffffffu, pp, o);
            qp += __shfl_xor_sync(0xffffffffu, qp, o);
        }
        if (l == 0) { sq[w] = qq; sp[w] = pp; sc[w] = qp; }
        __syncthreads();
        if (t == 0) {
            float QQ = 0.f, PP = 0.f, QP = 0.f;
            #pragma unroll
            for (int i = 0; i < 8; i++) { QQ += sq[i]; PP += sp[i]; QP += sc[i]; }
            float qn = sqrtf(QQ), pn = sqrtf(PP);
            g_pos[b] = QP / fmaxf(qn * pn, 1e-6f);
            s_inv = (qn > 0.f) ? (1.0f / qn) : 0.f;
        }
        __syncthreads();
        float inv = s_inv;
        __half2 lo = __floats2half2_rn(a.x * inv, a.y * inv);
        __half2 hi = __floats2half2_rn(a.z * inv, a.w * inv);
        __half2* dst = reinterpret_cast<__half2*>(g_Qh) + (size_t)b * (D_ / 2) + t * 2;
        dst[0] = lo; dst[1] = hi;
    } else {
        int b = bid - B_;
        float4 a = reinterpret_cast<const float4*>(n + (size_t)b * D_)[t];
        float nn = a.x*a.x + a.y*a.y + a.z*a.z + a.w*a.w;
        #pragma unroll
        for (int o = 16; o > 0; o >>= 1) nn += __shfl_xor_sync(0xffffffffu, nn, o);
        if (l == 0) sq[w] = nn;
        __syncthreads();
        if (t == 0) {
            float NN = 0.f;
            #pragma unroll
            for (int i = 0; i < 8; i++) NN += sq[i];
            float qn = sqrtf(NN);
            s_inv = (qn > 0.f) ? (1.0f / qn) : 0.f;
        }
        __syncthreads();
        float inv = s_inv;
        __half2 lo = __floats2half2_rn(a.x * inv, a.y * inv);
        __half2 hi = __floats2half2_rn(a.z * inv, a.w * inv);
        __half2* dst = reinterpret_cast<__half2*>(g_Nh) + (size_t)b * (D_ / 2) + t * 2;
        dst[0] = lo; dst[1] = hi;
    }
}

// ---------------------------------------------------------------------------
// poly exp on [-1.2, 1.2] (deg-9 Taylor, FMA pipe only)
// ---------------------------------------------------------------------------
__device__ __forceinline__ float poly_exp(float x) {
    float e = 2.7557319e-6f;
    e = fmaf(e, x, 2.4801587e-5f);
    e = fmaf(e, x, 1.9841270e-4f);
    e = fmaf(e, x, 1.3888889e-3f);
    e = fmaf(e, x, 8.3333333e-3f);
    e = fmaf(e, x, 4.1666668e-2f);
    e = fmaf(e, x, 1.6666667e-1f);
    e = fmaf(e, x, 0.5f);
    e = fmaf(e, x, 1.0f);
    e = fmaf(e, x, 1.0f);
    return e;
}

__device__ __forceinline__ void cpa16(uint32_t dst_smem, const void* src) {
    asm volatile("cp.async.cg.shared.global [%0], [%1], 16;" :: "r"(dst_smem), "l"(src));
}

#define LDSM4(r0, r1, r2, r3, addr) \
    asm volatile("ldmatrix.sync.aligned.m8n8.x4.shared.b16 {%0,%1,%2,%3}, [%4];" \
        : "=r"(r0), "=r"(r1), "=r"(r2), "=r"(r3) : "r"(addr))

// fp16 accumulate: D (2 regs, 4 halves) = A (4 regs) * B (2 regs) + D
#define MMA_F16ACC(d, av, b0, b1) \
    asm volatile("mma.sync.aligned.m16n8k16.row.col.f16.f16.f16.f16 " \
        "{%0,%1}, {%2,%3,%4,%5}, {%6,%7}, {%0,%1};" \
        : "+r"((d)[0]), "+r"((d)[1]) \
        : "r"((av)[0]), "r"((av)[1]), "r"((av)[2]), "r"((av)[3]), "r"(b0), "r"(b1))

// ---------------------------------------------------------------------------
// Kernel 2: fp16 mma.sync GEMM (fp16 accumulate), 128x128 block tile,
// 32x32 warp tile, BK=64, 2-stage cp.async pipeline, 2 CTAs/SM.
// grid = (NNEG/128, B_/128), block = 512 (16 warps as 4x4)
// ---------------------------------------------------------------------------
__global__ __launch_bounds__(512, 2) void k_gemm() {
    extern __shared__ __align__(16) char smem_raw[];
    float* Cf = reinterpret_cast<float*>(smem_raw);
    const uint32_t sbase = (uint32_t)__cvta_generic_to_shared(smem_raw);

    const int t = threadIdx.x;
    const int warp = t >> 5, lane = t & 31;
    const int wm = warp >> 2;   // 0..3 : 32-row strip
    const int wn = warp & 3;    // 0..3 : 32-col strip
    const int bx = blockIdx.x, by = blockIdx.y;

    const __half* Aptr = g_Qh + (size_t)by * BM * D_;
    const __half* Bptr = g_Nh + (size_t)bx * BN * D_;

    auto load_stage = [&](int slot, int k0) {
        uint32_t base = sbase + (uint32_t)slot * STAGE_B;
        #pragma unroll
        for (int i = 0; i < 2; i++) {
            int c = t + 512 * i;
            int r = c >> 3, c16 = c & 7;
            cpa16(base + (uint32_t)(r * LDK + c16 * 16),
                  Aptr + (size_t)r * D_ + k0 + c16 * 8);
        }
        #pragma unroll
        for (int i = 2; i < 4; i++) {
            int c = t + 512 * i;
            int r = c >> 3, c16 = c & 7;
            cpa16(base + (uint32_t)(r * LDK + c16 * 16),
                  Bptr + (size_t)(r - 128) * D_ + k0 + c16 * 8);
        }
    };

    const uint32_t lrow16 = (uint32_t)((lane & 7) | (((lane >> 3) & 1) << 3));
    const uint32_t lbyteA = (uint32_t)((lane >> 4) * 16);
    const int btile = lane >> 3, bnrow = lane & 7;

    uint32_t aoff[2], boff[2];
    #pragma unroll
    for (int s = 0; s < 2; s++)
        aoff[s] = (uint32_t)((wm * 32 + s * 16 + (int)lrow16) * LDK) + lbyteA;
    #pragma unroll
    for (int p = 0; p < 2; p++) {
        int strip = 2 * p + (btile >> 1);
        boff[p] = (uint32_t)(128 * LDK + (wn * 32 + strip * 8 + bnrow) * LDK
                             + (btile & 1) * 16);
    }

    uint32_t afr[2][4];
    uint32_t bfr[2][4];
    uint32_t acc[2][4][2] = {};

    load_stage(0, 0);
    asm volatile("cp.async.commit_group;");

    for (int it = 0; it < NIT; it++) {
        const int cur = it & 1;
        if (it + 1 < NIT) load_stage(cur ^ 1, (it + 1) * BK);
        asm volatile("cp.async.commit_group;");
        asm volatile("cp.async.wait_group 1;");
        __syncthreads();

        const uint32_t base = sbase + (uint32_t)cur * STAGE_B;
        #pragma unroll
        for (int kk = 0; kk < 4; kk++) {
            uint32_t ko = (uint32_t)(kk * 32);
            #pragma unroll
            for (int s = 0; s < 2; s++)
                LDSM4(afr[s][0], afr[s][1], afr[s][2], afr[s][3],
                      base + aoff[s] + ko);
            #pragma unroll
            for (int p = 0; p < 2; p++)
                LDSM4(bfr[p][0], bfr[p][1], bfr[p][2], bfr[p][3],
                      base + boff[p] + ko);
            #pragma unroll
            for (int mi = 0; mi < 2; mi++)
                #pragma unroll
                for (int nj = 0; nj < 4; nj++) {
                    const uint32_t* bp = &bfr[nj >> 1][(nj & 1) * 2];
                    MMA_F16ACC(acc[mi][nj], afr[mi], bp[0], bp[1]);
                }
        }
        __syncthreads();
    }

    // store accumulators (half2 -> float) to smem C (pipeline smem is dead)
    const int g = lane >> 2, tt = lane & 3;
    #pragma unroll
    for (int mi = 0; mi < 2; mi++)
        #pragma unroll
        for (int nj = 0; nj < 4; nj++) {
            int row0 = wm * 32 + mi * 16 + g;
            int col  = wn * 32 + nj * 8 + tt * 2;
            float2 v01 = __half22float2(*reinterpret_cast<__half2*>(&acc[mi][nj][0]));
            float2 v23 = __half22float2(*reinterpret_cast<__half2*>(&acc[mi][nj][1]));
            *reinterpret_cast<float2*>(&Cf[(size_t)row0 * EPI_LD + col]) = v01;
            *reinterpret_cast<float2*>(&Cf[(size_t)(row0 + 8) * EPI_LD + col]) = v23;
        }
    __syncthreads();

    // fused exp + row partial sums: 4 threads per row, 32 cols each
    const int row = t >> 2, seg = t & 3;
    const float* cr = &Cf[(size_t)row * EPI_LD + seg * 32];
    float s = 0.f;
    #pragma unroll
    for (int j = 0; j < 32; j++)
        s += poly_exp(cr[j] * c_invT);
    s += __shfl_xor_sync(0xffffffffu, s, 1);
    s += __shfl_xor_sync(0xffffffffu, s, 2);
    if (seg == 0)
        g_part[(size_t)(by * BM + row) * NTILES + bx] = s;  // deterministic
}

// ---------------------------------------------------------------------------
// Kernel 3 (fused loss + final reduce, last-block-done):
// grid = 32 blocks x 256 threads; each thread owns one row. Block partials
// are reduced in double; the last block to finish combines all 32 partials
// in fixed index order (deterministic) and writes the scalar. The ticket
// counter self-resets so every graph replay starts from zero.
// ---------------------------------------------------------------------------
__global__ void k_loss(float* __restrict__ out) {
    const int t = threadIdx.x, bid = blockIdx.x;
    const int b = bid * 256 + t;

    const float4* pr = reinterpret_cast<const float4*>(&g_part[(size_t)b * NTILES]);
    float s2s = 0.f;
    #pragma unroll
    for (int j = 0; j < NTILES / 4; j++) {
        float4 v = pr[j];
        s2s += v.x + v.y + v.z + v.w;
    }
    float s2 = s2s * (1.0f / (float)NNEG);
    float s1 = expf(g_pos[b] * c_invT);
    double acc = (double)log1pf(s2 / s1);

    // block reduce (double)
    #pragma unroll
    for (int o = 16; o > 0; o >>= 1) acc += __shfl_xor_sync(0xffffffffu, acc, o);
    __shared__ double sd[8];
    __shared__ int is_last;
    if ((t & 31) == 0) sd[t >> 5] = acc;
    __syncthreads();
    if (t == 0) {
        double blk = 0.0;
        #pragma unroll
        for (int i = 0; i < 8; i++) blk += sd[i];
        g_blk[bid] = blk;
        __threadfence();
        unsigned int old = atomicAdd(&g_sem, 1u);
        is_last = (old == NLBLK - 1) ? 1 : 0;
        if (is_last) g_sem = 0;   // self-reset for next graph replay
    }
    __syncthreads();
    if (is_last && t == 0) {
        double tot = 0.0;
        #pragma unroll
        for (int i = 0; i < NLBLK; i++) tot += g_blk[i];  // fixed order
        out[0] = (float)(tot / (double)B_);
    }
}

// ---------------------------------------------------------------------------
extern "C" void kernel_launch(void* const* d_in, const int* in_sizes, int n_in,
                              void* d_out, int out_size) {
    const float* q = (const float*)d_in[0];
    const float* p = (const float*)d_in[1];
    const float* n = (const float*)d_in[2];
    float* out = (float*)d_out;

    cudaFuncSetAttribute(k_gemm, cudaFuncAttributeMaxDynamicSharedMemorySize, SMEM_BYTES);

    k_norm<<<B_ + NNEG, 256>>>(q, p, n);
    k_gemm<<<dim3(NNEG / BN, B_ / BM), 512, SMEM_BYTES>>>();
    k_loss<<<NLBLK, 256>>>(out);
}